// round 15
// baseline (speedup 1.0000x reference)
#include <cuda_runtime.h>
#include <cuda_fp16.h>
#include <math.h>
#include <stdint.h>

// Problem dims (fixed)
#define BB 2
#define SS 2048
#define HH 1024
#define NHH 16
#define DHH 64
#define FFF 4096
#define MM (BB*SS)   // 4096 tokens
#define H3 (3*HH)    // 3072

// Q-side fold: 1/sqrt(dh) * log2(e)  (applied to Wq,bq at prep time)
#define QSCALE 0.18033688011112042f

// ---------------- scratch (device globals; no allocation allowed) ----------
__device__ __half g_ln1h [MM*HH];
__device__ __half g_qkvh [MM*H3];
__device__ __half g_attnh[MM*HH];
__device__ float  g_xatt [MM*HH];
__device__ __half g_ln2h [MM*HH];
__device__ __half g_midh [MM*FFF];
// transposed fp16 weights, stored [N][K] (K-major)
__device__ __half g_wqkvh[H3*HH];
__device__ __half g_woh  [HH*HH];
__device__ __half g_w1h  [FFF*HH];
__device__ __half g_w2h  [HH*FFF];
__device__ float  g_bqkv [H3];

// ---------------- helpers ----------------------------------------------------
__device__ __forceinline__ float gelu_exact(float v) {
    return 0.5f * v * (1.0f + erff(v * 0.70710678118654752f));
}

__device__ __forceinline__ float ex2(float x) {
    float r;
    asm("ex2.approx.f32 %0, %1;" : "=f"(r) : "f"(x));
    return r;
}

__device__ __forceinline__ void mma_h(float* d, const unsigned* a,
                                      unsigned b0, unsigned b1) {
    asm volatile(
        "mma.sync.aligned.m16n8k16.row.col.f32.f16.f16.f32 "
        "{%0,%1,%2,%3}, {%4,%5,%6,%7}, {%8,%9}, {%0,%1,%2,%3};\n"
        : "+f"(d[0]), "+f"(d[1]), "+f"(d[2]), "+f"(d[3])
        : "r"(a[0]), "r"(a[1]), "r"(a[2]), "r"(a[3]), "r"(b0), "r"(b1));
}

__device__ __forceinline__ void ldsm_x4(unsigned* r, uint32_t a) {
    asm volatile("ldmatrix.sync.aligned.m8n8.x4.shared.b16 {%0,%1,%2,%3}, [%4];"
        : "=r"(r[0]), "=r"(r[1]), "=r"(r[2]), "=r"(r[3]) : "r"(a));
}
__device__ __forceinline__ void ldsm_x4t(unsigned* r, uint32_t a) {
    asm volatile("ldmatrix.sync.aligned.m8n8.x4.trans.shared.b16 {%0,%1,%2,%3}, [%4];"
        : "=r"(r[0]), "=r"(r[1]), "=r"(r[2]), "=r"(r[3]) : "r"(a));
}

__device__ __forceinline__ void cp16h(__half* dst, const __half* src) {
    unsigned s = (unsigned)__cvta_generic_to_shared(dst);
    asm volatile("cp.async.cg.shared.global [%0], [%1], 16;\n" :: "r"(s), "l"(src));
}

__device__ __forceinline__ unsigned packh2(float a, float b) {
    __half2 h = __floats2half2_rn(a, b);
    return *(unsigned*)&h;
}

// ---------------- one-shot weight + bias prep (single launch) ----------------
// Wq and bq are pre-scaled by QSCALE (folds attention scale + log2e into Q).
__global__ void prep_weights(const float* __restrict__ Wq, const float* __restrict__ Wk,
                             const float* __restrict__ Wv, const float* __restrict__ Wo,
                             const float* __restrict__ W1, const float* __restrict__ W2,
                             const float* __restrict__ bq, const float* __restrict__ bk,
                             const float* __restrict__ bv,
                             __half* __restrict__ wqkv, __half* __restrict__ wo,
                             __half* __restrict__ w1,   __half* __restrict__ w2,
                             float* __restrict__ bqkv) {
    int bid = blockIdx.x;
    if (bid >= 12288) {   // bias concat blocks
        int i = (bid - 12288) * 256 + threadIdx.y * 32 + threadIdx.x;
        if (i < H3) {
            const float* src = (i < HH) ? bq : (i < 2*HH) ? bk : bv;
            float v = src[i & (HH - 1)];
            if (i < HH) v *= QSCALE;
            bqkv[i] = v;
        }
        return;
    }
    __shared__ float t[32][33];
    const float* src; __half* dst; int K, N, b0i; float sc = 1.0f;
    if      (bid < 1024) { src = Wq; dst = wqkv;           K = HH;  N = HH;  b0i = 0;    sc = QSCALE; }
    else if (bid < 2048) { src = Wk; dst = wqkv + HH*HH;   K = HH;  N = HH;  b0i = 1024; }
    else if (bid < 3072) { src = Wv; dst = wqkv + 2*HH*HH; K = HH;  N = HH;  b0i = 2048; }
    else if (bid < 4096) { src = Wo; dst = wo;             K = HH;  N = HH;  b0i = 3072; }
    else if (bid < 8192) { src = W1; dst = w1;             K = HH;  N = FFF; b0i = 4096; }
    else                 { src = W2; dst = w2;             K = FFF; N = HH;  b0i = 8192; }
    int lb = bid - b0i;
    int gx = N / 32;
    int n0 = (lb % gx) * 32, k0 = (lb / gx) * 32;
    int x = threadIdx.x, y = threadIdx.y;     // 32 x 8
    #pragma unroll
    for (int i = 0; i < 32; i += 8)
        t[y + i][x] = src[(size_t)(k0 + y + i) * N + n0 + x];
    __syncthreads();
    #pragma unroll
    for (int i = 0; i < 32; i += 8)
        dst[(size_t)(n0 + y + i) * K + k0 + x] = __float2half_rn(t[x][y + i] * sc);
}

// ---------------- layernorm (fp16 output) ------------------------------------
__device__ __forceinline__ float block_reduce_sum(float v) {
    __shared__ float sh[8];
    int lane = threadIdx.x & 31, w = threadIdx.x >> 5;
    #pragma unroll
    for (int o = 16; o > 0; o >>= 1) v += __shfl_xor_sync(0xffffffffu, v, o);
    if (lane == 0) sh[w] = v;
    __syncthreads();
    float t = (threadIdx.x < 8) ? sh[threadIdx.x] : 0.0f;
    if (w == 0) {
        #pragma unroll
        for (int o = 4; o > 0; o >>= 1) t += __shfl_xor_sync(0xffffffffu, t, o);
        if (lane == 0) sh[0] = t;
    }
    __syncthreads();
    float r = sh[0];
    __syncthreads();
    return r;
}

__global__ void ln_kernel(const float* __restrict__ x,
                          const float* __restrict__ g,
                          const float* __restrict__ be,
                          __half* __restrict__ out) {
    int row = blockIdx.x;
    int t = threadIdx.x;
    const float4* xr = (const float4*)(x + (size_t)row * HH);
    float4 v = xr[t];
    float s = v.x + v.y + v.z + v.w;
    float mu = block_reduce_sum(s) * (1.0f / HH);
    float dx = v.x - mu, dy = v.y - mu, dz = v.z - mu, dw = v.w - mu;
    float ss = dx*dx + dy*dy + dz*dz + dw*dw;
    float var = block_reduce_sum(ss) * (1.0f / HH);
    float rstd = rsqrtf(var + 1e-5f);
    float4 gg = ((const float4*)g)[t];
    float4 bb = ((const float4*)be)[t];
    __half2* orow = (__half2*)(out + (size_t)row * HH);
    orow[t*2]     = __floats2half2_rn(dx * rstd * gg.x + bb.x, dy * rstd * gg.y + bb.y);
    orow[t*2 + 1] = __floats2half2_rn(dz * rstd * gg.z + bb.z, dw * rstd * gg.w + bb.w);
}

// ---------------- fp16 tensor-core GEMM (64x64 warp tiles, BK=32, 4-stage) ---
#define AHS 40                 // smem row stride in halfs (80B): conflict-free
#define NSTG 4
#define OPHS (128 * AHS)       // halfs per operand per stage
#define SMEMG (NSTG * 2 * OPHS * 2)   // bytes = 81920

template<int EPI, int OUTH>
__global__ void __launch_bounds__(128, 2)
gemmh(const __half* __restrict__ A, const __half* __restrict__ Bt,
      const float* __restrict__ bias, const float* __restrict__ res,
      void* __restrict__ Cv, int M, int N, int K) {
    extern __shared__ __half dsm[];
    __half* As = dsm;
    __half* Bs = dsm + NSTG * OPHS;

    int tid = threadIdx.x, warp = tid >> 5, lane = tid & 31;
    int l8 = lane & 7;
    int gq = lane >> 2, t4 = lane & 3;
    int wmb = (warp >> 1) * 64, wnb = (warp & 1) * 64;
    int m0 = blockIdx.y * 128, n0 = blockIdx.x * 128;

    float acc[4][8][4] = {};
    int NC = K >> 5;

    uint32_t asb = (uint32_t)__cvta_generic_to_shared(As);
    uint32_t bsb = (uint32_t)__cvta_generic_to_shared(Bs);
    const uint32_t stgB = OPHS * 2;

    int a_r  = l8 + ((lane >> 3) & 1) * 8;
    int a_c8 = (lane >> 4) * 8;
    int b_n  = (lane >> 4) * 8 + l8;
    int b_c8 = ((lane >> 3) & 1) * 8;

    #define LOAD_CHUNK(ch) do {                                                 \
        int _s = (ch) % NSTG; int _k0 = (ch) * 32;                              \
        __half* _as = As + _s * OPHS; __half* _bs = Bs + _s * OPHS;             \
        _Pragma("unroll")                                                       \
        for (int _q = 0; _q < 4; _q++) {                                        \
            int _fid = tid + _q * 128;                                          \
            int _row = _fid >> 2, _seg = _fid & 3;                              \
            cp16h(_as + _row * AHS + _seg*8, A  + (size_t)(m0 + _row) * K + _k0 + _seg*8); \
            cp16h(_bs + _row * AHS + _seg*8, Bt + (size_t)(n0 + _row) * K + _k0 + _seg*8); \
        }                                                                       \
    } while (0)

    #pragma unroll
    for (int c = 0; c < NSTG - 1; c++) {
        LOAD_CHUNK(c);
        asm volatile("cp.async.commit_group;");
    }

    for (int c = 0; c < NC; c++) {
        asm volatile("cp.async.wait_group %0;" :: "n"(NSTG - 2));
        __syncthreads();

        if (c + NSTG - 1 < NC) LOAD_CHUNK(c + NSTG - 1);
        asm volatile("cp.async.commit_group;");

        uint32_t asc = asb + (uint32_t)(c % NSTG) * stgB;
        uint32_t bsc = bsb + (uint32_t)(c % NSTG) * stgB;
        #pragma unroll
        for (int ks = 0; ks < 2; ks++) {
            int kk = ks * 16;
            unsigned a[4][4], bf[4][4];
            #pragma unroll
            for (int mi = 0; mi < 4; mi++) {
                int row = wmb + mi * 16 + a_r;
                ldsm_x4(a[mi], asc + (uint32_t)(row * AHS + kk + a_c8) * 2);
            }
            #pragma unroll
            for (int p = 0; p < 4; p++) {
                int row = wnb + p * 16 + b_n;
                ldsm_x4(bf[p], bsc + (uint32_t)(row * AHS + kk + b_c8) * 2);
            }
            #pragma unroll
            for (int p = 0; p < 4; p++) {
                #pragma unroll
                for (int mi = 0; mi < 4; mi++) {
                    mma_h(acc[mi][2*p],     a[mi], bf[p][0], bf[p][1]);
                    mma_h(acc[mi][2*p + 1], a[mi], bf[p][2], bf[p][3]);
                }
            }
        }
    }
    #undef LOAD_CHUNK

    #pragma unroll
    for (int mi = 0; mi < 4; mi++) {
        int row = m0 + wmb + mi * 16 + gq;
        #pragma unroll
        for (int nj = 0; nj < 8; nj++) {
            int col = n0 + wnb + nj * 8 + 2*t4;
            float b0 = bias[col], b1 = bias[col + 1];
            float v0 = acc[mi][nj][0] + b0;
            float v1 = acc[mi][nj][1] + b1;
            float v2 = acc[mi][nj][2] + b0;
            float v3 = acc[mi][nj][3] + b1;
            if (EPI == 1) {
                v0 = gelu_exact(v0); v1 = gelu_exact(v1);
                v2 = gelu_exact(v2); v3 = gelu_exact(v3);
            }
            if (EPI == 2) {
                float2 r0 = *(const float2*)(res + (size_t)row * N + col);
                float2 r1 = *(const float2*)(res + (size_t)(row + 8) * N + col);
                v0 += r0.x; v1 += r0.y; v2 += r1.x; v3 += r1.y;
            }
            if (OUTH) {
                __half* C = (__half*)Cv;
                *(__half2*)(C + (size_t)row * N + col) = __floats2half2_rn(v0, v1);
                *(__half2*)(C + (size_t)(row + 8) * N + col) = __floats2half2_rn(v2, v3);
            } else {
                float* C = (float*)Cv;
                *(float2*)(C + (size_t)row * N + col)       = make_float2(v0, v1);
                *(float2*)(C + (size_t)(row + 8) * N + col) = make_float2(v2, v3);
            }
        }
    }
}

// ---------------- fp16 flash attention (32 Q-rows/warp, exp2, 2-buffer) ------
// Br=128 (4 warps x 32 rows), Bc=64. Q pre-scaled by 0.125*log2e via Wq.
// Warp-uniform rescale skip: when no row max changed, corr==1 exactly.
#define FVS 72

__global__ void __launch_bounds__(128, 2)
flash_h(const __half* __restrict__ QKV, __half* __restrict__ O) {
    __shared__ __half Ks[2][64][FVS];
    __shared__ __half Vs[2][64][FVS];

    int tid = threadIdx.x, warp = tid >> 5, lane = tid & 31;
    int l8 = lane & 7;
    int gq = lane >> 2, t4 = lane & 3;
    int qt = gridDim.x - 1 - blockIdx.x;          // heavy tiles first
    int bh = blockIdx.y, b = bh >> 4, h = bh & 15;
    size_t rowbase = (size_t)b * SS * H3;
    int qoff = h * 64, koff = HH + h * 64, voff = 2 * HH + h * 64;
    int qbase = qt * 128 + warp * 32;             // this warp's 32 q-rows

    uint32_t ksb = (uint32_t)__cvta_generic_to_shared(&Ks[0][0][0]);
    uint32_t vsb = (uint32_t)__cvta_generic_to_shared(&Vs[0][0][0]);
    const uint32_t fstgB = 64 * FVS * 2;

    int b_n  = (lane >> 4) * 8 + l8;
    int b_c8 = ((lane >> 3) & 1) * 8;
    int v_r  = ((lane >> 3) & 1) * 8 + l8;
    int v_d  = (lane >> 4) * 8;

    #define FLOAD(j) do {                                                        \
        int _s = (j) & 1;                                                        \
        _Pragma("unroll")                                                        \
        for (int _it = 0; _it < 4; _it++) {                                      \
            int _fid = tid + _it * 128;                                          \
            int _r = _fid >> 3, _sg = _fid & 7;                                  \
            cp16h(&Ks[_s][_r][_sg*8],                                            \
                  QKV + rowbase + (size_t)((j)*64 + _r) * H3 + koff + _sg*8);    \
            cp16h(&Vs[_s][_r][_sg*8],                                            \
                  QKV + rowbase + (size_t)((j)*64 + _r) * H3 + voff + _sg*8);    \
        }                                                                        \
    } while (0)

    // Q fragments for both 16-row groups (A: rows 0-15, B: rows 16-31)
    unsigned qfA[4][4], qfB[4][4];
    #pragma unroll
    for (int kc = 0; kc < 4; kc++) {
        const __half* qa0 = QKV + rowbase + (size_t)(qbase + gq)      * H3 + qoff + kc*16 + 2*t4;
        const __half* qa1 = QKV + rowbase + (size_t)(qbase + gq + 8)  * H3 + qoff + kc*16 + 2*t4;
        const __half* qb0 = QKV + rowbase + (size_t)(qbase + gq + 16) * H3 + qoff + kc*16 + 2*t4;
        const __half* qb1 = QKV + rowbase + (size_t)(qbase + gq + 24) * H3 + qoff + kc*16 + 2*t4;
        qfA[kc][0] = *(const unsigned*)qa0;
        qfA[kc][1] = *(const unsigned*)qa1;
        qfA[kc][2] = *(const unsigned*)(qa0 + 8);
        qfA[kc][3] = *(const unsigned*)(qa1 + 8);
        qfB[kc][0] = *(const unsigned*)qb0;
        qfB[kc][1] = *(const unsigned*)qb1;
        qfB[kc][2] = *(const unsigned*)(qb0 + 8);
        qfB[kc][3] = *(const unsigned*)(qb1 + 8);
    }

    float oA[8][4] = {}, oB[8][4] = {};
    float mA0 = -1e30f, mA1 = -1e30f, lA0 = 0.0f, lA1 = 0.0f;
    float mB0 = -1e30f, mB1 = -1e30f, lB0 = 0.0f, lB1 = 0.0f;
    int rA0 = qbase + gq, rA1 = rA0 + 8, rB0 = rA0 + 16, rB1 = rA0 + 24;

    int jmax = 2 * qt + 1;
    FLOAD(0);
    asm volatile("cp.async.commit_group;");

    for (int j = 0; j <= jmax; j++) {
        asm volatile("cp.async.wait_group 0;");
        __syncthreads();

        if (j < jmax) FLOAD(j + 1);
        asm volatile("cp.async.commit_group;");

        if (j * 64 <= qbase + 31) {
            uint32_t ksj = ksb + (uint32_t)(j & 1) * fstgB;
            uint32_t vsj = vsb + (uint32_t)(j & 1) * fstgB;

            float sA[8][4] = {}, sB[8][4] = {};
            #pragma unroll
            for (int kc = 0; kc < 4; kc++) {
                #pragma unroll
                for (int p = 0; p < 4; p++) {
                    unsigned kb[4];
                    int row = p * 16 + b_n;
                    ldsm_x4(kb, ksj + (uint32_t)(row * FVS + kc*16 + b_c8) * 2);
                    mma_h(sA[2*p],     qfA[kc], kb[0], kb[1]);
                    mma_h(sA[2*p + 1], qfA[kc], kb[2], kb[3]);
                    mma_h(sB[2*p],     qfB[kc], kb[0], kb[1]);
                    mma_h(sB[2*p + 1], qfB[kc], kb[2], kb[3]);
                }
            }

            float mtA0 = -1e30f, mtA1 = -1e30f, mtB0 = -1e30f, mtB1 = -1e30f;
            if (j * 64 + 63 > qbase) {
                #pragma unroll
                for (int nj = 0; nj < 8; nj++) {
                    int c0 = j*64 + nj*8 + 2*t4, c1 = c0 + 1;
                    if (c0 > rA0) sA[nj][0] = -1e30f;
                    if (c1 > rA0) sA[nj][1] = -1e30f;
                    if (c0 > rA1) sA[nj][2] = -1e30f;
                    if (c1 > rA1) sA[nj][3] = -1e30f;
                    if (c0 > rB0) sB[nj][0] = -1e30f;
                    if (c1 > rB0) sB[nj][1] = -1e30f;
                    if (c0 > rB1) sB[nj][2] = -1e30f;
                    if (c1 > rB1) sB[nj][3] = -1e30f;
                    mtA0 = fmaxf(mtA0, fmaxf(sA[nj][0], sA[nj][1]));
                    mtA1 = fmaxf(mtA1, fmaxf(sA[nj][2], sA[nj][3]));
                    mtB0 = fmaxf(mtB0, fmaxf(sB[nj][0], sB[nj][1]));
                    mtB1 = fmaxf(mtB1, fmaxf(sB[nj][2], sB[nj][3]));
                }
            } else {
                #pragma unroll
                for (int nj = 0; nj < 8; nj++) {
                    mtA0 = fmaxf(mtA0, fmaxf(sA[nj][0], sA[nj][1]));
                    mtA1 = fmaxf(mtA1, fmaxf(sA[nj][2], sA[nj][3]));
                    mtB0 = fmaxf(mtB0, fmaxf(sB[nj][0], sB[nj][1]));
                    mtB1 = fmaxf(mtB1, fmaxf(sB[nj][2], sB[nj][3]));
                }
            }
            mtA0 = fmaxf(mtA0, __shfl_xor_sync(0xffffffffu, mtA0, 1));
            mtA0 = fmaxf(mtA0, __shfl_xor_sync(0xffffffffu, mtA0, 2));
            mtA1 = fmaxf(mtA1, __shfl_xor_sync(0xffffffffu, mtA1, 1));
            mtA1 = fmaxf(mtA1, __shfl_xor_sync(0xffffffffu, mtA1, 2));
            mtB0 = fmaxf(mtB0, __shfl_xor_sync(0xffffffffu, mtB0, 1));
            mtB0 = fmaxf(mtB0, __shfl_xor_sync(0xffffffffu, mtB0, 2));
            mtB1 = fmaxf(mtB1, __shfl_xor_sync(0xffffffffu, mtB1, 1));
            mtB1 = fmaxf(mtB1, __shfl_xor_sync(0xffffffffu, mtB1, 2));

            float nA0 = fmaxf(mA0, mtA0), nA1 = fmaxf(mA1, mtA1);
            float nB0 = fmaxf(mB0, mtB0), nB1 = fmaxf(mB1, mtB1);

            // warp-uniform rescale skip: only pay corr when any max changed
            bool ch = (nA0 != mA0) || (nA1 != mA1) || (nB0 != mB0) || (nB1 != mB1);
            if (__any_sync(0xffffffffu, ch)) {
                float cA0 = ex2(mA0 - nA0), cA1 = ex2(mA1 - nA1);
                float cB0 = ex2(mB0 - nB0), cB1 = ex2(mB1 - nB1);
                lA0 *= cA0; lA1 *= cA1; lB0 *= cB0; lB1 *= cB1;
                #pragma unroll
                for (int nd = 0; nd < 8; nd++) {
                    oA[nd][0] *= cA0; oA[nd][1] *= cA0;
                    oA[nd][2] *= cA1; oA[nd][3] *= cA1;
                    oB[nd][0] *= cB0; oB[nd][1] *= cB0;
                    oB[nd][2] *= cB1; oB[nd][3] *= cB1;
                }
            }
            mA0 = nA0; mA1 = nA1; mB0 = nB0; mB1 = nB1;

            float rsA0 = 0.0f, rsA1 = 0.0f, rsB0 = 0.0f, rsB1 = 0.0f;
            #pragma unroll
            for (int nj = 0; nj < 8; nj++) {
                float a0 = ex2(sA[nj][0] - nA0);
                float a1 = ex2(sA[nj][1] - nA0);
                float a2 = ex2(sA[nj][2] - nA1);
                float a3 = ex2(sA[nj][3] - nA1);
                float b0 = ex2(sB[nj][0] - nB0);
                float b1 = ex2(sB[nj][1] - nB0);
                float b2 = ex2(sB[nj][2] - nB1);
                float b3 = ex2(sB[nj][3] - nB1);
                sA[nj][0] = a0; sA[nj][1] = a1; sA[nj][2] = a2; sA[nj][3] = a3;
                sB[nj][0] = b0; sB[nj][1] = b1; sB[nj][2] = b2; sB[nj][3] = b3;
                rsA0 += a0 + a1; rsA1 += a2 + a3;
                rsB0 += b0 + b1; rsB1 += b2 + b3;
            }
            rsA0 += __shfl_xor_sync(0xffffffffu, rsA0, 1);
            rsA0 += __shfl_xor_sync(0xffffffffu, rsA0, 2);
            rsA1 += __shfl_xor_sync(0xffffffffu, rsA1, 1);
            rsA1 += __shfl_xor_sync(0xffffffffu, rsA1, 2);
            rsB0 += __shfl_xor_sync(0xffffffffu, rsB0, 1);
            rsB0 += __shfl_xor_sync(0xffffffffu, rsB0, 2);
            rsB1 += __shfl_xor_sync(0xffffffffu, rsB1, 1);
            rsB1 += __shfl_xor_sync(0xffffffffu, rsB1, 2);
            lA0 += rsA0;  lA1 += rsA1;
            lB0 += rsB0;  lB1 += rsB1;

            #pragma unroll
            for (int kc = 0; kc < 4; kc++) {
                unsigned paA[4], paB[4];
                paA[0] = packh2(sA[2*kc][0],     sA[2*kc][1]);
                paA[1] = packh2(sA[2*kc][2],     sA[2*kc][3]);
                paA[2] = packh2(sA[2*kc + 1][0], sA[2*kc + 1][1]);
                paA[3] = packh2(sA[2*kc + 1][2], sA[2*kc + 1][3]);
                paB[0] = packh2(sB[2*kc][0],     sB[2*kc][1]);
                paB[1] = packh2(sB[2*kc][2],     sB[2*kc][3]);
                paB[2] = packh2(sB[2*kc + 1][0], sB[2*kc + 1][1]);
                paB[3] = packh2(sB[2*kc + 1][2], sB[2*kc + 1][3]);
                #pragma unroll
                for (int p = 0; p < 4; p++) {
                    unsigned vb[4];
                    int row = kc * 16 + v_r;
                    ldsm_x4t(vb, vsj + (uint32_t)(row * FVS + p * 16 + v_d) * 2);
                    mma_h(oA[2*p],     paA, vb[0], vb[1]);
                    mma_h(oA[2*p + 1], paA, vb[2], vb[3]);
                    mma_h(oB[2*p],     paB, vb[0], vb[1]);
                    mma_h(oB[2*p + 1], paB, vb[2], vb[3]);
                }
            }
        }
    }
    #undef FLOAD

    float iA0 = 1.0f / lA0, iA1 = 1.0f / lA1;
    float iB0 = 1.0f / lB0, iB1 = 1.0f / lB1;
    size_t obase = (size_t)(b * SS) * HH + h * 64;
    #pragma unroll
    for (int nd = 0; nd < 8; nd++) {
        *(__half2*)(O + obase + (size_t)rA0 * HH + nd*8 + 2*t4) =
            __floats2half2_rn(oA[nd][0] * iA0, oA[nd][1] * iA0);
        *(__half2*)(O + obase + (size_t)rA1 * HH + nd*8 + 2*t4) =
            __floats2half2_rn(oA[nd][2] * iA1, oA[nd][3] * iA1);
        *(__half2*)(O + obase + (size_t)rB0 * HH + nd*8 + 2*t4) =
            __floats2half2_rn(oB[nd][0] * iB0, oB[nd][1] * iB0);
        *(__half2*)(O + obase + (size_t)rB1 * HH + nd*8 + 2*t4) =
            __floats2half2_rn(oB[nd][2] * iB1, oB[nd][3] * iB1);
    }
}

// ---------------- launch ----------------------------------------------------
extern "C" void kernel_launch(void* const* d_in, const int* in_sizes, int n_in,
                              void* d_out, int out_size) {
    const float* x   = (const float*)d_in[0];
    const float* Wq  = (const float*)d_in[1];
    const float* bq  = (const float*)d_in[2];
    const float* Wk  = (const float*)d_in[3];
    const float* bk  = (const float*)d_in[4];
    const float* Wv  = (const float*)d_in[5];
    const float* bv  = (const float*)d_in[6];
    const float* Wo  = (const float*)d_in[7];
    const float* bo  = (const float*)d_in[8];
    const float* W1  = (const float*)d_in[9];
    const float* b1  = (const float*)d_in[10];
    const float* W2  = (const float*)d_in[11];
    const float* b2  = (const float*)d_in[12];
    const float* g1  = (const float*)d_in[13];
    const float* be1 = (const float*)d_in[14];
    const float* g2  = (const float*)d_in[15];
    const float* be2 = (const float*)d_in[16];
    float* out = (float*)d_out;

    __half *p_ln1h, *p_qkvh, *p_attnh, *p_ln2h, *p_midh;
    __half *p_wqkvh, *p_woh, *p_w1h, *p_w2h;
    float *p_xatt, *p_bqkv;
    cudaGetSymbolAddress((void**)&p_ln1h,  g_ln1h);
    cudaGetSymbolAddress((void**)&p_qkvh,  g_qkvh);
    cudaGetSymbolAddress((void**)&p_attnh, g_attnh);
    cudaGetSymbolAddress((void**)&p_xatt,  g_xatt);
    cudaGetSymbolAddress((void**)&p_ln2h,  g_ln2h);
    cudaGetSymbolAddress((void**)&p_midh,  g_midh);
    cudaGetSymbolAddress((void**)&p_wqkvh, g_wqkvh);
    cudaGetSymbolAddress((void**)&p_woh,   g_woh);
    cudaGetSymbolAddress((void**)&p_w1h,   g_w1h);
    cudaGetSymbolAddress((void**)&p_w2h,   g_w2h);
    cudaGetSymbolAddress((void**)&p_bqkv,  g_bqkv);

    cudaFuncSetAttribute(gemmh<0,1>, cudaFuncAttributeMaxDynamicSharedMemorySize, SMEMG);
    cudaFuncSetAttribute(gemmh<1,1>, cudaFuncAttributeMaxDynamicSharedMemorySize, SMEMG);
    cudaFuncSetAttribute(gemmh<2,0>, cudaFuncAttributeMaxDynamicSharedMemorySize, SMEMG);

    // 0) weight + bias prep in one launch (Wq/bq pre-scaled by QSCALE)
    prep_weights<<<12300, dim3(32, 8)>>>(Wq, Wk, Wv, Wo, W1, W2, bq, bk, bv,
                                         p_wqkvh, p_woh, p_w1h, p_w2h, p_bqkv);

    // 1) LN1 -> fp16
    ln_kernel<<<MM, 256>>>(x, g1, be1, p_ln1h);

    // 2) fused QKV projection
    gemmh<0,1><<<dim3(H3/128, MM/128), 128, SMEMG>>>(p_ln1h, p_wqkvh, p_bqkv, nullptr,
                                                     p_qkvh, MM, H3, HH);

    // 3) fp16 causal flash attention (32 rows/warp, exp2, rescale-skip)
    flash_h<<<dim3(SS/128, BB*NHH), 128>>>(p_qkvh, p_attnh);

    // 4) O projection + residual (fp32 out)
    gemmh<2,0><<<dim3(HH/128, MM/128), 128, SMEMG>>>(p_attnh, p_woh, bo, x,
                                                     p_xatt, MM, HH, HH);

    // 5) LN2 -> fp16
    ln_kernel<<<MM, 256>>>(p_xatt, g2, be2, p_ln2h);

    // 6) FFN up + exact GELU (fp16 out)
    gemmh<1,1><<<dim3(FFF/128, MM/128), 128, SMEMG>>>(p_ln2h, p_w1h, b1, nullptr,
                                                      p_midh, MM, FFF, HH);

    // 7) FFN down + residual (fp32 out)
    gemmh<2,0><<<dim3(HH/128, MM/128), 128, SMEMG>>>(p_midh, p_w2h, b2, p_xatt,
                                                     out, MM, HH, FFF);
}

// round 17
// speedup vs baseline: 1.0150x; 1.0150x over previous
#include <cuda_runtime.h>
#include <cuda_fp16.h>
#include <math.h>
#include <stdint.h>

// Problem dims (fixed)
#define BB 2
#define SS 2048
#define HH 1024
#define NHH 16
#define DHH 64
#define FFF 4096
#define MM (BB*SS)   // 4096 tokens
#define H3 (3*HH)    // 3072

// Q-side fold: 1/sqrt(dh) * log2(e)  (applied to Wq,bq at prep time)
#define QSCALE 0.18033688011112042f

// ---------------- scratch (device globals; no allocation allowed) ----------
__device__ __half g_ln1h [MM*HH];
__device__ __half g_qkvh [MM*H3];
__device__ __half g_attnh[MM*HH];
__device__ float  g_xatt [MM*HH];
__device__ __half g_ln2h [MM*HH];
__device__ __half g_midh [MM*FFF];
// transposed fp16 weights, stored [N][K] (K-major)
__device__ __half g_wqkvh[H3*HH];
__device__ __half g_woh  [HH*HH];
__device__ __half g_w1h  [FFF*HH];
__device__ __half g_w2h  [HH*FFF];
__device__ float  g_bqkv [H3];

// ---------------- helpers ----------------------------------------------------
__device__ __forceinline__ float gelu_exact(float v) {
    return 0.5f * v * (1.0f + erff(v * 0.70710678118654752f));
}

__device__ __forceinline__ float ex2(float x) {
    float r;
    asm("ex2.approx.f32 %0, %1;" : "=f"(r) : "f"(x));
    return r;
}

__device__ __forceinline__ void mma_h(float* d, const unsigned* a,
                                      unsigned b0, unsigned b1) {
    asm volatile(
        "mma.sync.aligned.m16n8k16.row.col.f32.f16.f16.f32 "
        "{%0,%1,%2,%3}, {%4,%5,%6,%7}, {%8,%9}, {%0,%1,%2,%3};\n"
        : "+f"(d[0]), "+f"(d[1]), "+f"(d[2]), "+f"(d[3])
        : "r"(a[0]), "r"(a[1]), "r"(a[2]), "r"(a[3]), "r"(b0), "r"(b1));
}

__device__ __forceinline__ void ldsm_x4(unsigned* r, uint32_t a) {
    asm volatile("ldmatrix.sync.aligned.m8n8.x4.shared.b16 {%0,%1,%2,%3}, [%4];"
        : "=r"(r[0]), "=r"(r[1]), "=r"(r[2]), "=r"(r[3]) : "r"(a));
}
__device__ __forceinline__ void ldsm_x4t(unsigned* r, uint32_t a) {
    asm volatile("ldmatrix.sync.aligned.m8n8.x4.trans.shared.b16 {%0,%1,%2,%3}, [%4];"
        : "=r"(r[0]), "=r"(r[1]), "=r"(r[2]), "=r"(r[3]) : "r"(a));
}

__device__ __forceinline__ void cp16h(__half* dst, const __half* src) {
    unsigned s = (unsigned)__cvta_generic_to_shared(dst);
    asm volatile("cp.async.cg.shared.global [%0], [%1], 16;\n" :: "r"(s), "l"(src));
}

__device__ __forceinline__ unsigned packh2(float a, float b) {
    __half2 h = __floats2half2_rn(a, b);
    return *(unsigned*)&h;
}

// ---------------- one-shot weight + bias prep (single launch) ----------------
// Wq and bq are pre-scaled by QSCALE (folds attention scale + log2e into Q).
__global__ void prep_weights(const float* __restrict__ Wq, const float* __restrict__ Wk,
                             const float* __restrict__ Wv, const float* __restrict__ Wo,
                             const float* __restrict__ W1, const float* __restrict__ W2,
                             const float* __restrict__ bq, const float* __restrict__ bk,
                             const float* __restrict__ bv,
                             __half* __restrict__ wqkv, __half* __restrict__ wo,
                             __half* __restrict__ w1,   __half* __restrict__ w2,
                             float* __restrict__ bqkv) {
    int bid = blockIdx.x;
    if (bid >= 12288) {   // bias concat blocks
        int i = (bid - 12288) * 256 + threadIdx.y * 32 + threadIdx.x;
        if (i < H3) {
            const float* src = (i < HH) ? bq : (i < 2*HH) ? bk : bv;
            float v = src[i & (HH - 1)];
            if (i < HH) v *= QSCALE;
            bqkv[i] = v;
        }
        return;
    }
    __shared__ float t[32][33];
    const float* src; __half* dst; int K, N, b0i; float sc = 1.0f;
    if      (bid < 1024) { src = Wq; dst = wqkv;           K = HH;  N = HH;  b0i = 0;    sc = QSCALE; }
    else if (bid < 2048) { src = Wk; dst = wqkv + HH*HH;   K = HH;  N = HH;  b0i = 1024; }
    else if (bid < 3072) { src = Wv; dst = wqkv + 2*HH*HH; K = HH;  N = HH;  b0i = 2048; }
    else if (bid < 4096) { src = Wo; dst = wo;             K = HH;  N = HH;  b0i = 3072; }
    else if (bid < 8192) { src = W1; dst = w1;             K = HH;  N = FFF; b0i = 4096; }
    else                 { src = W2; dst = w2;             K = FFF; N = HH;  b0i = 8192; }
    int lb = bid - b0i;
    int gx = N / 32;
    int n0 = (lb % gx) * 32, k0 = (lb / gx) * 32;
    int x = threadIdx.x, y = threadIdx.y;     // 32 x 8
    #pragma unroll
    for (int i = 0; i < 32; i += 8)
        t[y + i][x] = src[(size_t)(k0 + y + i) * N + n0 + x];
    __syncthreads();
    #pragma unroll
    for (int i = 0; i < 32; i += 8)
        dst[(size_t)(n0 + y + i) * K + k0 + x] = __float2half_rn(t[x][y + i] * sc);
}

// ---------------- layernorm: one warp per row (no barriers, no smem) ---------
__global__ void __launch_bounds__(256)
ln_kernel(const float* __restrict__ x,
          const float* __restrict__ g,
          const float* __restrict__ be,
          __half* __restrict__ out) {
    int warp = threadIdx.x >> 5, lane = threadIdx.x & 31;
    int row = blockIdx.x * 8 + warp;
    const float4* xr = (const float4*)(x + (size_t)row * HH);

    float4 v[8];
    float s = 0.0f;
    #pragma unroll
    for (int i = 0; i < 8; i++) {
        v[i] = xr[lane + i * 32];
        s += v[i].x + v[i].y + v[i].z + v[i].w;
    }
    #pragma unroll
    for (int o = 16; o > 0; o >>= 1) s += __shfl_xor_sync(0xffffffffu, s, o);
    float mu = s * (1.0f / HH);

    float ss = 0.0f;
    #pragma unroll
    for (int i = 0; i < 8; i++) {
        float dx = v[i].x - mu, dy = v[i].y - mu;
        float dz = v[i].z - mu, dw = v[i].w - mu;
        ss += dx*dx + dy*dy + dz*dz + dw*dw;
    }
    #pragma unroll
    for (int o = 16; o > 0; o >>= 1) ss += __shfl_xor_sync(0xffffffffu, ss, o);
    float rstd = rsqrtf(ss * (1.0f / HH) + 1e-5f);

    __half2* orow = (__half2*)(out + (size_t)row * HH);
    const float4* g4 = (const float4*)g;
    const float4* b4 = (const float4*)be;
    #pragma unroll
    for (int i = 0; i < 8; i++) {
        int idx = lane + i * 32;
        float4 gg = g4[idx], bb = b4[idx];
        orow[idx*2]     = __floats2half2_rn((v[i].x - mu) * rstd * gg.x + bb.x,
                                            (v[i].y - mu) * rstd * gg.y + bb.y);
        orow[idx*2 + 1] = __floats2half2_rn((v[i].z - mu) * rstd * gg.z + bb.z,
                                            (v[i].w - mu) * rstd * gg.w + bb.w);
    }
}

// ---------------- fp16 tensor-core GEMM (64x64 warp tiles, BK=32, 4-stage) ---
#define AHS 40                 // smem row stride in halfs (80B): conflict-free
#define NSTG 4
#define OPHS (128 * AHS)       // halfs per operand per stage
#define SMEMG (NSTG * 2 * OPHS * 2)   // bytes = 81920

template<int EPI, int OUTH>
__global__ void __launch_bounds__(128, 2)
gemmh(const __half* __restrict__ A, const __half* __restrict__ Bt,
      const float* __restrict__ bias, const float* __restrict__ res,
      void* __restrict__ Cv, int M, int N, int K) {
    extern __shared__ __half dsm[];
    __half* As = dsm;
    __half* Bs = dsm + NSTG * OPHS;

    int tid = threadIdx.x, warp = tid >> 5, lane = tid & 31;
    int l8 = lane & 7;
    int gq = lane >> 2, t4 = lane & 3;
    int wmb = (warp >> 1) * 64, wnb = (warp & 1) * 64;
    int m0 = blockIdx.y * 128, n0 = blockIdx.x * 128;

    float acc[4][8][4] = {};
    int NC = K >> 5;

    uint32_t asb = (uint32_t)__cvta_generic_to_shared(As);
    uint32_t bsb = (uint32_t)__cvta_generic_to_shared(Bs);
    const uint32_t stgB = OPHS * 2;

    int a_r  = l8 + ((lane >> 3) & 1) * 8;
    int a_c8 = (lane >> 4) * 8;
    int b_n  = (lane >> 4) * 8 + l8;
    int b_c8 = ((lane >> 3) & 1) * 8;

    #define LOAD_CHUNK(ch) do {                                                 \
        int _s = (ch) % NSTG; int _k0 = (ch) * 32;                              \
        __half* _as = As + _s * OPHS; __half* _bs = Bs + _s * OPHS;             \
        _Pragma("unroll")                                                       \
        for (int _q = 0; _q < 4; _q++) {                                        \
            int _fid = tid + _q * 128;                                          \
            int _row = _fid >> 2, _seg = _fid & 3;                              \
            cp16h(_as + _row * AHS + _seg*8, A  + (size_t)(m0 + _row) * K + _k0 + _seg*8); \
            cp16h(_bs + _row * AHS + _seg*8, Bt + (size_t)(n0 + _row) * K + _k0 + _seg*8); \
        }                                                                       \
    } while (0)

    #pragma unroll
    for (int c = 0; c < NSTG - 1; c++) {
        LOAD_CHUNK(c);
        asm volatile("cp.async.commit_group;");
    }

    for (int c = 0; c < NC; c++) {
        asm volatile("cp.async.wait_group %0;" :: "n"(NSTG - 2));
        __syncthreads();

        if (c + NSTG - 1 < NC) LOAD_CHUNK(c + NSTG - 1);
        asm volatile("cp.async.commit_group;");

        uint32_t asc = asb + (uint32_t)(c % NSTG) * stgB;
        uint32_t bsc = bsb + (uint32_t)(c % NSTG) * stgB;
        #pragma unroll
        for (int ks = 0; ks < 2; ks++) {
            int kk = ks * 16;
            unsigned a[4][4], bf[4][4];
            #pragma unroll
            for (int mi = 0; mi < 4; mi++) {
                int row = wmb + mi * 16 + a_r;
                ldsm_x4(a[mi], asc + (uint32_t)(row * AHS + kk + a_c8) * 2);
            }
            #pragma unroll
            for (int p = 0; p < 4; p++) {
                int row = wnb + p * 16 + b_n;
                ldsm_x4(bf[p], bsc + (uint32_t)(row * AHS + kk + b_c8) * 2);
            }
            #pragma unroll
            for (int p = 0; p < 4; p++) {
                #pragma unroll
                for (int mi = 0; mi < 4; mi++) {
                    mma_h(acc[mi][2*p],     a[mi], bf[p][0], bf[p][1]);
                    mma_h(acc[mi][2*p + 1], a[mi], bf[p][2], bf[p][3]);
                }
            }
        }
    }
    #undef LOAD_CHUNK

    #pragma unroll
    for (int mi = 0; mi < 4; mi++) {
        int row = m0 + wmb + mi * 16 + gq;
        #pragma unroll
        for (int nj = 0; nj < 8; nj++) {
            int col = n0 + wnb + nj * 8 + 2*t4;
            float b0 = bias[col], b1 = bias[col + 1];
            float v0 = acc[mi][nj][0] + b0;
            float v1 = acc[mi][nj][1] + b1;
            float v2 = acc[mi][nj][2] + b0;
            float v3 = acc[mi][nj][3] + b1;
            if (EPI == 1) {
                v0 = gelu_exact(v0); v1 = gelu_exact(v1);
                v2 = gelu_exact(v2); v3 = gelu_exact(v3);
            }
            if (EPI == 2) {
                float2 r0 = *(const float2*)(res + (size_t)row * N + col);
                float2 r1 = *(const float2*)(res + (size_t)(row + 8) * N + col);
                v0 += r0.x; v1 += r0.y; v2 += r1.x; v3 += r1.y;
            }
            if (OUTH) {
                __half* C = (__half*)Cv;
                *(__half2*)(C + (size_t)row * N + col) = __floats2half2_rn(v0, v1);
                *(__half2*)(C + (size_t)(row + 8) * N + col) = __floats2half2_rn(v2, v3);
            } else {
                float* C = (float*)Cv;
                *(float2*)(C + (size_t)row * N + col)       = make_float2(v0, v1);
                *(float2*)(C + (size_t)(row + 8) * N + col) = make_float2(v2, v3);
            }
        }
    }
}

// ---------------- fp16 flash attention (32 Q-rows/warp, exp2, 2-buffer) ------
// Br=128 (4 warps x 32 rows), Bc=64. Q pre-scaled by 0.125*log2e via Wq.
#define FVS 72

__global__ void __launch_bounds__(128, 2)
flash_h(const __half* __restrict__ QKV, __half* __restrict__ O) {
    __shared__ __half Ks[2][64][FVS];
    __shared__ __half Vs[2][64][FVS];

    int tid = threadIdx.x, warp = tid >> 5, lane = tid & 31;
    int l8 = lane & 7;
    int gq = lane >> 2, t4 = lane & 3;
    int qt = gridDim.x - 1 - blockIdx.x;          // heavy tiles first
    int bh = blockIdx.y, b = bh >> 4, h = bh & 15;
    size_t rowbase = (size_t)b * SS * H3;
    int qoff = h * 64, koff = HH + h * 64, voff = 2 * HH + h * 64;
    int qbase = qt * 128 + warp * 32;             // this warp's 32 q-rows

    uint32_t ksb = (uint32_t)__cvta_generic_to_shared(&Ks[0][0][0]);
    uint32_t vsb = (uint32_t)__cvta_generic_to_shared(&Vs[0][0][0]);
    const uint32_t fstgB = 64 * FVS * 2;

    int b_n  = (lane >> 4) * 8 + l8;
    int b_c8 = ((lane >> 3) & 1) * 8;
    int v_r  = ((lane >> 3) & 1) * 8 + l8;
    int v_d  = (lane >> 4) * 8;

    #define FLOAD(j) do {                                                        \
        int _s = (j) & 1;                                                        \
        _Pragma("unroll")                                                        \
        for (int _it = 0; _it < 4; _it++) {                                      \
            int _fid = tid + _it * 128;                                          \
            int _r = _fid >> 3, _sg = _fid & 7;                                  \
            cp16h(&Ks[_s][_r][_sg*8],                                            \
                  QKV + rowbase + (size_t)((j)*64 + _r) * H3 + koff + _sg*8);    \
            cp16h(&Vs[_s][_r][_sg*8],                                            \
                  QKV + rowbase + (size_t)((j)*64 + _r) * H3 + voff + _sg*8);    \
        }                                                                        \
    } while (0)

    // Q fragments for both 16-row groups (A: rows 0-15, B: rows 16-31)
    unsigned qfA[4][4], qfB[4][4];
    #pragma unroll
    for (int kc = 0; kc < 4; kc++) {
        const __half* qa0 = QKV + rowbase + (size_t)(qbase + gq)      * H3 + qoff + kc*16 + 2*t4;
        const __half* qa1 = QKV + rowbase + (size_t)(qbase + gq + 8)  * H3 + qoff + kc*16 + 2*t4;
        const __half* qb0 = QKV + rowbase + (size_t)(qbase + gq + 16) * H3 + qoff + kc*16 + 2*t4;
        const __half* qb1 = QKV + rowbase + (size_t)(qbase + gq + 24) * H3 + qoff + kc*16 + 2*t4;
        qfA[kc][0] = *(const unsigned*)qa0;
        qfA[kc][1] = *(const unsigned*)qa1;
        qfA[kc][2] = *(const unsigned*)(qa0 + 8);
        qfA[kc][3] = *(const unsigned*)(qa1 + 8);
        qfB[kc][0] = *(const unsigned*)qb0;
        qfB[kc][1] = *(const unsigned*)qb1;
        qfB[kc][2] = *(const unsigned*)(qb0 + 8);
        qfB[kc][3] = *(const unsigned*)(qb1 + 8);
    }

    float oA[8][4] = {}, oB[8][4] = {};
    float mA0 = -1e30f, mA1 = -1e30f, lA0 = 0.0f, lA1 = 0.0f;
    float mB0 = -1e30f, mB1 = -1e30f, lB0 = 0.0f, lB1 = 0.0f;
    int rA0 = qbase + gq, rA1 = rA0 + 8, rB0 = rA0 + 16, rB1 = rA0 + 24;

    int jmax = 2 * qt + 1;
    FLOAD(0);
    asm volatile("cp.async.commit_group;");

    for (int j = 0; j <= jmax; j++) {
        asm volatile("cp.async.wait_group 0;");
        __syncthreads();

        if (j < jmax) FLOAD(j + 1);
        asm volatile("cp.async.commit_group;");

        if (j * 64 <= qbase + 31) {
            uint32_t ksj = ksb + (uint32_t)(j & 1) * fstgB;
            uint32_t vsj = vsb + (uint32_t)(j & 1) * fstgB;

            float sA[8][4] = {}, sB[8][4] = {};
            #pragma unroll
            for (int kc = 0; kc < 4; kc++) {
                #pragma unroll
                for (int p = 0; p < 4; p++) {
                    unsigned kb[4];
                    int row = p * 16 + b_n;
                    ldsm_x4(kb, ksj + (uint32_t)(row * FVS + kc*16 + b_c8) * 2);
                    mma_h(sA[2*p],     qfA[kc], kb[0], kb[1]);
                    mma_h(sA[2*p + 1], qfA[kc], kb[2], kb[3]);
                    mma_h(sB[2*p],     qfB[kc], kb[0], kb[1]);
                    mma_h(sB[2*p + 1], qfB[kc], kb[2], kb[3]);
                }
            }

            float mtA0 = -1e30f, mtA1 = -1e30f, mtB0 = -1e30f, mtB1 = -1e30f;
            if (j * 64 + 63 > qbase) {
                #pragma unroll
                for (int nj = 0; nj < 8; nj++) {
                    int c0 = j*64 + nj*8 + 2*t4, c1 = c0 + 1;
                    if (c0 > rA0) sA[nj][0] = -1e30f;
                    if (c1 > rA0) sA[nj][1] = -1e30f;
                    if (c0 > rA1) sA[nj][2] = -1e30f;
                    if (c1 > rA1) sA[nj][3] = -1e30f;
                    if (c0 > rB0) sB[nj][0] = -1e30f;
                    if (c1 > rB0) sB[nj][1] = -1e30f;
                    if (c0 > rB1) sB[nj][2] = -1e30f;
                    if (c1 > rB1) sB[nj][3] = -1e30f;
                    mtA0 = fmaxf(mtA0, fmaxf(sA[nj][0], sA[nj][1]));
                    mtA1 = fmaxf(mtA1, fmaxf(sA[nj][2], sA[nj][3]));
                    mtB0 = fmaxf(mtB0, fmaxf(sB[nj][0], sB[nj][1]));
                    mtB1 = fmaxf(mtB1, fmaxf(sB[nj][2], sB[nj][3]));
                }
            } else {
                #pragma unroll
                for (int nj = 0; nj < 8; nj++) {
                    mtA0 = fmaxf(mtA0, fmaxf(sA[nj][0], sA[nj][1]));
                    mtA1 = fmaxf(mtA1, fmaxf(sA[nj][2], sA[nj][3]));
                    mtB0 = fmaxf(mtB0, fmaxf(sB[nj][0], sB[nj][1]));
                    mtB1 = fmaxf(mtB1, fmaxf(sB[nj][2], sB[nj][3]));
                }
            }
            mtA0 = fmaxf(mtA0, __shfl_xor_sync(0xffffffffu, mtA0, 1));
            mtA0 = fmaxf(mtA0, __shfl_xor_sync(0xffffffffu, mtA0, 2));
            mtA1 = fmaxf(mtA1, __shfl_xor_sync(0xffffffffu, mtA1, 1));
            mtA1 = fmaxf(mtA1, __shfl_xor_sync(0xffffffffu, mtA1, 2));
            mtB0 = fmaxf(mtB0, __shfl_xor_sync(0xffffffffu, mtB0, 1));
            mtB0 = fmaxf(mtB0, __shfl_xor_sync(0xffffffffu, mtB0, 2));
            mtB1 = fmaxf(mtB1, __shfl_xor_sync(0xffffffffu, mtB1, 1));
            mtB1 = fmaxf(mtB1, __shfl_xor_sync(0xffffffffu, mtB1, 2));

            float nA0 = fmaxf(mA0, mtA0), nA1 = fmaxf(mA1, mtA1);
            float nB0 = fmaxf(mB0, mtB0), nB1 = fmaxf(mB1, mtB1);
            float cA0 = ex2(mA0 - nA0), cA1 = ex2(mA1 - nA1);
            float cB0 = ex2(mB0 - nB0), cB1 = ex2(mB1 - nB1);
            mA0 = nA0; mA1 = nA1; mB0 = nB0; mB1 = nB1;

            float rsA0 = 0.0f, rsA1 = 0.0f, rsB0 = 0.0f, rsB1 = 0.0f;
            #pragma unroll
            for (int nj = 0; nj < 8; nj++) {
                float a0 = ex2(sA[nj][0] - nA0);
                float a1 = ex2(sA[nj][1] - nA0);
                float a2 = ex2(sA[nj][2] - nA1);
                float a3 = ex2(sA[nj][3] - nA1);
                float b0 = ex2(sB[nj][0] - nB0);
                float b1 = ex2(sB[nj][1] - nB0);
                float b2 = ex2(sB[nj][2] - nB1);
                float b3 = ex2(sB[nj][3] - nB1);
                sA[nj][0] = a0; sA[nj][1] = a1; sA[nj][2] = a2; sA[nj][3] = a3;
                sB[nj][0] = b0; sB[nj][1] = b1; sB[nj][2] = b2; sB[nj][3] = b3;
                rsA0 += a0 + a1; rsA1 += a2 + a3;
                rsB0 += b0 + b1; rsB1 += b2 + b3;
            }
            rsA0 += __shfl_xor_sync(0xffffffffu, rsA0, 1);
            rsA0 += __shfl_xor_sync(0xffffffffu, rsA0, 2);
            rsA1 += __shfl_xor_sync(0xffffffffu, rsA1, 1);
            rsA1 += __shfl_xor_sync(0xffffffffu, rsA1, 2);
            rsB0 += __shfl_xor_sync(0xffffffffu, rsB0, 1);
            rsB0 += __shfl_xor_sync(0xffffffffu, rsB0, 2);
            rsB1 += __shfl_xor_sync(0xffffffffu, rsB1, 1);
            rsB1 += __shfl_xor_sync(0xffffffffu, rsB1, 2);
            lA0 = lA0 * cA0 + rsA0;  lA1 = lA1 * cA1 + rsA1;
            lB0 = lB0 * cB0 + rsB0;  lB1 = lB1 * cB1 + rsB1;

            #pragma unroll
            for (int nd = 0; nd < 8; nd++) {
                oA[nd][0] *= cA0; oA[nd][1] *= cA0;
                oA[nd][2] *= cA1; oA[nd][3] *= cA1;
                oB[nd][0] *= cB0; oB[nd][1] *= cB0;
                oB[nd][2] *= cB1; oB[nd][3] *= cB1;
            }

            #pragma unroll
            for (int kc = 0; kc < 4; kc++) {
                unsigned paA[4], paB[4];
                paA[0] = packh2(sA[2*kc][0],     sA[2*kc][1]);
                paA[1] = packh2(sA[2*kc][2],     sA[2*kc][3]);
                paA[2] = packh2(sA[2*kc + 1][0], sA[2*kc + 1][1]);
                paA[3] = packh2(sA[2*kc + 1][2], sA[2*kc + 1][3]);
                paB[0] = packh2(sB[2*kc][0],     sB[2*kc][1]);
                paB[1] = packh2(sB[2*kc][2],     sB[2*kc][3]);
                paB[2] = packh2(sB[2*kc + 1][0], sB[2*kc + 1][1]);
                paB[3] = packh2(sB[2*kc + 1][2], sB[2*kc + 1][3]);
                #pragma unroll
                for (int p = 0; p < 4; p++) {
                    unsigned vb[4];
                    int row = kc * 16 + v_r;
                    ldsm_x4t(vb, vsj + (uint32_t)(row * FVS + p * 16 + v_d) * 2);
                    mma_h(oA[2*p],     paA, vb[0], vb[1]);
                    mma_h(oA[2*p + 1], paA, vb[2], vb[3]);
                    mma_h(oB[2*p],     paB, vb[0], vb[1]);
                    mma_h(oB[2*p + 1], paB, vb[2], vb[3]);
                }
            }
        }
    }
    #undef FLOAD

    float iA0 = 1.0f / lA0, iA1 = 1.0f / lA1;
    float iB0 = 1.0f / lB0, iB1 = 1.0f / lB1;
    size_t obase = (size_t)(b * SS) * HH + h * 64;
    #pragma unroll
    for (int nd = 0; nd < 8; nd++) {
        *(__half2*)(O + obase + (size_t)rA0 * HH + nd*8 + 2*t4) =
            __floats2half2_rn(oA[nd][0] * iA0, oA[nd][1] * iA0);
        *(__half2*)(O + obase + (size_t)rA1 * HH + nd*8 + 2*t4) =
            __floats2half2_rn(oA[nd][2] * iA1, oA[nd][3] * iA1);
        *(__half2*)(O + obase + (size_t)rB0 * HH + nd*8 + 2*t4) =
            __floats2half2_rn(oB[nd][0] * iB0, oB[nd][1] * iB0);
        *(__half2*)(O + obase + (size_t)rB1 * HH + nd*8 + 2*t4) =
            __floats2half2_rn(oB[nd][2] * iB1, oB[nd][3] * iB1);
    }
}

// ---------------- launch ----------------------------------------------------
extern "C" void kernel_launch(void* const* d_in, const int* in_sizes, int n_in,
                              void* d_out, int out_size) {
    const float* x   = (const float*)d_in[0];
    const float* Wq  = (const float*)d_in[1];
    const float* bq  = (const float*)d_in[2];
    const float* Wk  = (const float*)d_in[3];
    const float* bk  = (const float*)d_in[4];
    const float* Wv  = (const float*)d_in[5];
    const float* bv  = (const float*)d_in[6];
    const float* Wo  = (const float*)d_in[7];
    const float* bo  = (const float*)d_in[8];
    const float* W1  = (const float*)d_in[9];
    const float* b1  = (const float*)d_in[10];
    const float* W2  = (const float*)d_in[11];
    const float* b2  = (const float*)d_in[12];
    const float* g1  = (const float*)d_in[13];
    const float* be1 = (const float*)d_in[14];
    const float* g2  = (const float*)d_in[15];
    const float* be2 = (const float*)d_in[16];
    float* out = (float*)d_out;

    __half *p_ln1h, *p_qkvh, *p_attnh, *p_ln2h, *p_midh;
    __half *p_wqkvh, *p_woh, *p_w1h, *p_w2h;
    float *p_xatt, *p_bqkv;
    cudaGetSymbolAddress((void**)&p_ln1h,  g_ln1h);
    cudaGetSymbolAddress((void**)&p_qkvh,  g_qkvh);
    cudaGetSymbolAddress((void**)&p_attnh, g_attnh);
    cudaGetSymbolAddress((void**)&p_xatt,  g_xatt);
    cudaGetSymbolAddress((void**)&p_ln2h,  g_ln2h);
    cudaGetSymbolAddress((void**)&p_midh,  g_midh);
    cudaGetSymbolAddress((void**)&p_wqkvh, g_wqkvh);
    cudaGetSymbolAddress((void**)&p_woh,   g_woh);
    cudaGetSymbolAddress((void**)&p_w1h,   g_w1h);
    cudaGetSymbolAddress((void**)&p_w2h,   g_w2h);
    cudaGetSymbolAddress((void**)&p_bqkv,  g_bqkv);

    cudaFuncSetAttribute(gemmh<0,1>, cudaFuncAttributeMaxDynamicSharedMemorySize, SMEMG);
    cudaFuncSetAttribute(gemmh<1,1>, cudaFuncAttributeMaxDynamicSharedMemorySize, SMEMG);
    cudaFuncSetAttribute(gemmh<2,0>, cudaFuncAttributeMaxDynamicSharedMemorySize, SMEMG);

    // 0) weight + bias prep in one launch (Wq/bq pre-scaled by QSCALE)
    prep_weights<<<12300, dim3(32, 8)>>>(Wq, Wk, Wv, Wo, W1, W2, bq, bk, bv,
                                         p_wqkvh, p_woh, p_w1h, p_w2h, p_bqkv);

    // 1) LN1 -> fp16 (warp-per-row)
    ln_kernel<<<MM/8, 256>>>(x, g1, be1, p_ln1h);

    // 2) fused QKV projection
    gemmh<0,1><<<dim3(H3/128, MM/128), 128, SMEMG>>>(p_ln1h, p_wqkvh, p_bqkv, nullptr,
                                                     p_qkvh, MM, H3, HH);

    // 3) fp16 causal flash attention (32 rows/warp, exp2)
    flash_h<<<dim3(SS/128, BB*NHH), 128>>>(p_qkvh, p_attnh);

    // 4) O projection + residual (fp32 out)
    gemmh<2,0><<<dim3(HH/128, MM/128), 128, SMEMG>>>(p_attnh, p_woh, bo, x,
                                                     p_xatt, MM, HH, HH);

    // 5) LN2 -> fp16 (warp-per-row)
    ln_kernel<<<MM/8, 256>>>(p_xatt, g2, be2, p_ln2h);

    // 6) FFN up + exact GELU (fp16 out)
    gemmh<1,1><<<dim3(FFF/128, MM/128), 128, SMEMG>>>(p_ln2h, p_w1h, b1, nullptr,
                                                      p_midh, MM, FFF, HH);

    // 7) FFN down + residual (fp32 out)
    gemmh<2,0><<<dim3(HH/128, MM/128), 128, SMEMG>>>(p_midh, p_w2h, b2, p_xatt,
                                                     out, MM, HH, FFF);
}